// round 3
// baseline (speedup 1.0000x reference)
#include <cuda_runtime.h>
#include <cstdint>

#define NN 50000
#define EE 800000
#define DD 96
#define FF 128

// ---------------- scratch (static device globals; no allocs) ----------------
__device__ __align__(16) float g_hA[NN * DD];
__device__ __align__(16) float g_hB[NN * DD];
__device__ __align__(16) float g_T[NN * 3 * DD];   // [N][288]: root | rel0 | rel1
__device__ __align__(16) float g_WfT[FF * DD];
__device__ int g_deg[2 * NN];        // per (node, relation) segment counts
__device__ int g_cur[2 * NN];
__device__ int g_rowptr[2 * NN + 1];
__device__ int g_col[EE];

// ---------------- prep: zero counters + transpose Wf ----------------
__global__ void k_prep(const float* __restrict__ Wf, float* __restrict__ WfT,
                       int* __restrict__ deg, int* __restrict__ cur, int N2) {
    int i = blockIdx.x * blockDim.x + threadIdx.x;
    if (i < N2) { deg[i] = 0; cur[i] = 0; }
    if (i < DD * FF) {           // Wf is [d][k] row-major -> WfT [k][d]
        int d = i >> 7, k = i & 127;
        WfT[k * DD + d] = Wf[i];
    }
}

// ---------------- CSR build (2 edges per thread) ----------------
__global__ void k_hist(const int* __restrict__ ei, const float* __restrict__ attr,
                       int* __restrict__ deg, int E) {
    int e = (blockIdx.x * blockDim.x + threadIdx.x) * 2;
    if (e >= E) return;
    int2 d2 = *(const int2*)(ei + E + e);
    float4 a4 = *(const float4*)(attr + 2 * e);
    atomicAdd(&deg[2 * d2.x + (a4.y > a4.x ? 1 : 0)], 1);
    if (e + 1 < E)
        atomicAdd(&deg[2 * d2.y + (a4.w > a4.z ? 1 : 0)], 1);
}

__global__ void k_scan(const int* __restrict__ deg, int* __restrict__ rowptr, int N2) {
    __shared__ int part[1024];
    int tid = threadIdx.x;
    const int CH = (N2 + 1023) / 1024;
    int start = tid * CH;
    int end = start + CH; if (end > N2) end = N2; if (start > N2) start = N2;
    int s = 0;
    for (int i = start; i < end; i++) s += deg[i];
    part[tid] = s;
    __syncthreads();
    for (int off = 1; off < 1024; off <<= 1) {
        int v = (tid >= off) ? part[tid - off] : 0;
        __syncthreads();
        part[tid] += v;
        __syncthreads();
    }
    int excl = (tid == 0) ? 0 : part[tid - 1];
    for (int i = start; i < end; i++) { rowptr[i] = excl; excl += deg[i]; }
    if (tid == 1023) rowptr[N2] = part[1023];
}

__global__ void k_fill(const int* __restrict__ ei, const float* __restrict__ attr,
                       const int* __restrict__ rowptr, int* __restrict__ cur,
                       int* __restrict__ col, int E) {
    int e = (blockIdx.x * blockDim.x + threadIdx.x) * 2;
    if (e >= E) return;
    int2 s2 = *(const int2*)(ei + e);
    int2 d2 = *(const int2*)(ei + E + e);
    float4 a4 = *(const float4*)(attr + 2 * e);
    {
        int seg = 2 * d2.x + (a4.y > a4.x ? 1 : 0);
        int pos = __ldg(&rowptr[seg]) + atomicAdd(&cur[seg], 1);
        col[pos] = s2.x;
    }
    if (e + 1 < E) {
        int seg = 2 * d2.y + (a4.w > a4.z ? 1 : 0);
        int pos = __ldg(&rowptr[seg]) + atomicAdd(&cur[seg], 1);
        col[pos] = s2.y;
    }
}

// ---------------- tf32 tensor-core GEMM (convert at staging, reg double-buffer) ----
__device__ __forceinline__ uint32_t f2tf(float f) {
    uint32_t u; asm("cvt.rna.tf32.f32 %0, %1;" : "=r"(u) : "f"(f)); return u;
}
__device__ __forceinline__ void mma_tf32(float* c, const uint32_t* a, uint32_t b0, uint32_t b1) {
    asm volatile("mma.sync.aligned.m16n8k8.row.col.f32.tf32.tf32.f32 "
        "{%0,%1,%2,%3}, {%4,%5,%6,%7}, {%8,%9}, {%0,%1,%2,%3};"
        : "+f"(c[0]), "+f"(c[1]), "+f"(c[2]), "+f"(c[3])
        : "r"(a[0]), "r"(a[1]), "r"(a[2]), "r"(a[3]), "r"(b0), "r"(b1));
}

#define AS_LD 36   // padded row stride (words) for A smem
#define BS_LD 100  // padded row stride for B smem

__global__ __launch_bounds__(256) void k_gemm(
    const float* __restrict__ A, int M, int K,
    const float* __restrict__ B0, const float* __restrict__ B1, const float* __restrict__ B2,
    float* __restrict__ C, int ldc, const float* __restrict__ bias, int relu)
{
    __shared__ uint32_t As[128 * AS_LD];
    __shared__ uint32_t Bs[32 * BS_LD];
    const float* B = (blockIdx.y == 0) ? B0 : ((blockIdx.y == 1) ? B1 : B2);

    int tid = threadIdx.x;
    int lane = tid & 31;
    int warp = tid >> 5;
    int g = lane >> 2, tig = lane & 3;
    int mw = warp & 3;      // rows mw*32
    int nw = warp >> 2;     // cols nw*48
    int rowblock = blockIdx.x * 128;

    int ar[4], af[4], br_[3], bf_[3];
#pragma unroll
    for (int i = 0; i < 4; i++) { int id = tid + 256 * i; ar[i] = id >> 3; af[i] = id & 7; }
#pragma unroll
    for (int i = 0; i < 3; i++) { int id = tid + 256 * i; br_[i] = id / 24; bf_[i] = id % 24; }

    float c[2][6][4];
#pragma unroll
    for (int i = 0; i < 2; i++)
#pragma unroll
        for (int j = 0; j < 6; j++)
#pragma unroll
            for (int q = 0; q < 4; q++) c[i][j][q] = 0.f;

    const float4 z4 = make_float4(0.f, 0.f, 0.f, 0.f);
    float4 a_reg[4], b_reg[3];

    // prologue: load chunk 0
#pragma unroll
    for (int i = 0; i < 4; i++) {
        int gr = rowblock + ar[i];
        a_reg[i] = (gr < M) ? __ldg((const float4*)(A + (size_t)gr * K) + af[i]) : z4;
    }
#pragma unroll
    for (int i = 0; i < 3; i++)
        b_reg[i] = __ldg((const float4*)(B + (size_t)br_[i] * 96) + bf_[i]);
#pragma unroll
    for (int i = 0; i < 4; i++) {
        uint4 u = make_uint4(f2tf(a_reg[i].x), f2tf(a_reg[i].y), f2tf(a_reg[i].z), f2tf(a_reg[i].w));
        *(uint4*)(&As[ar[i] * AS_LD + af[i] * 4]) = u;
    }
#pragma unroll
    for (int i = 0; i < 3; i++) {
        uint4 u = make_uint4(f2tf(b_reg[i].x), f2tf(b_reg[i].y), f2tf(b_reg[i].z), f2tf(b_reg[i].w));
        *(uint4*)(&Bs[br_[i] * BS_LD + bf_[i] * 4]) = u;
    }
    __syncthreads();

    for (int kb = 0; kb < K; kb += 32) {
        bool more = (kb + 32 < K);
        if (more) {   // issue next-chunk LDGs before compute (latency overlap)
#pragma unroll
            for (int i = 0; i < 4; i++) {
                int gr = rowblock + ar[i];
                a_reg[i] = (gr < M) ? __ldg((const float4*)(A + (size_t)gr * K + kb + 32) + af[i]) : z4;
            }
#pragma unroll
            for (int i = 0; i < 3; i++)
                b_reg[i] = __ldg((const float4*)(B + (size_t)(kb + 32 + br_[i]) * 96) + bf_[i]);
        }
#pragma unroll
        for (int k8 = 0; k8 < 32; k8 += 8) {
            uint32_t a[2][4];
#pragma unroll
            for (int mt = 0; mt < 2; mt++) {
                int rb = mw * 32 + mt * 16;
                a[mt][0] = As[(rb + g) * AS_LD + k8 + tig];
                a[mt][1] = As[(rb + g + 8) * AS_LD + k8 + tig];
                a[mt][2] = As[(rb + g) * AS_LD + k8 + tig + 4];
                a[mt][3] = As[(rb + g + 8) * AS_LD + k8 + tig + 4];
            }
#pragma unroll
            for (int nt = 0; nt < 6; nt++) {
                int cb = nw * 48 + nt * 8;
                uint32_t b0 = Bs[(k8 + tig) * BS_LD + cb + g];
                uint32_t b1 = Bs[(k8 + tig + 4) * BS_LD + cb + g];
                mma_tf32(c[0][nt], a[0], b0, b1);
                mma_tf32(c[1][nt], a[1], b0, b1);
            }
        }
        __syncthreads();
        if (more) {
#pragma unroll
            for (int i = 0; i < 4; i++) {
                uint4 u = make_uint4(f2tf(a_reg[i].x), f2tf(a_reg[i].y), f2tf(a_reg[i].z), f2tf(a_reg[i].w));
                *(uint4*)(&As[ar[i] * AS_LD + af[i] * 4]) = u;
            }
#pragma unroll
            for (int i = 0; i < 3; i++) {
                uint4 u = make_uint4(f2tf(b_reg[i].x), f2tf(b_reg[i].y), f2tf(b_reg[i].z), f2tf(b_reg[i].w));
                *(uint4*)(&Bs[br_[i] * BS_LD + bf_[i] * 4]) = u;
            }
            __syncthreads();
        }
    }

    int colchunk = blockIdx.y * 96;
#pragma unroll
    for (int mt = 0; mt < 2; mt++) {
        int r0 = rowblock + mw * 32 + mt * 16 + g;
        int r1 = r0 + 8;
#pragma unroll
        for (int nt = 0; nt < 6; nt++) {
            int col = nw * 48 + nt * 8 + 2 * tig;
            float bx = 0.f, by = 0.f;
            if (bias) { bx = __ldg(bias + col); by = __ldg(bias + col + 1); }
            float v0 = c[mt][nt][0] + bx, v1 = c[mt][nt][1] + by;
            float v2 = c[mt][nt][2] + bx, v3 = c[mt][nt][3] + by;
            if (relu) {
                v0 = fmaxf(v0, 0.f); v1 = fmaxf(v1, 0.f);
                v2 = fmaxf(v2, 0.f); v3 = fmaxf(v3, 0.f);
            }
            if (r0 < M) *(float2*)(C + (size_t)r0 * ldc + colchunk + col) = make_float2(v0, v1);
            if (r1 < M) *(float2*)(C + (size_t)r1 * ldc + colchunk + col) = make_float2(v2, v3);
        }
    }
}

// ---------------- fused gather + mean + bias + relu (branch-free segments) --------
__global__ void k_aggout(const float* __restrict__ T, const int* __restrict__ rowptr,
                         const int* __restrict__ col, const float* __restrict__ bias,
                         float* __restrict__ out, int N) {
    int warpi = (blockIdx.x * blockDim.x + threadIdx.x) >> 5;
    int lane = threadIdx.x & 31;
    if (warpi >= N) return;
    int n = warpi;
    int e00 = __ldg(&rowptr[2 * n]);
    int e01 = __ldg(&rowptr[2 * n + 1]);
    int e11 = __ldg(&rowptr[2 * n + 2]);

    float x0 = 0.f, x1 = 0.f, x2 = 0.f;   // relation 0
    float y0 = 0.f, y1 = 0.f, y2 = 0.f;   // relation 1
    int e = e00;
    for (; e + 1 < e01; e += 2) {
        const float* ta = T + (size_t)__ldg(&col[e]) * 288 + 96;
        const float* tb = T + (size_t)__ldg(&col[e + 1]) * 288 + 96;
        x0 += __ldg(ta + lane) + __ldg(tb + lane);
        x1 += __ldg(ta + lane + 32) + __ldg(tb + lane + 32);
        x2 += __ldg(ta + lane + 64) + __ldg(tb + lane + 64);
    }
    if (e < e01) {
        const float* ta = T + (size_t)__ldg(&col[e]) * 288 + 96;
        x0 += __ldg(ta + lane);
        x1 += __ldg(ta + lane + 32);
        x2 += __ldg(ta + lane + 64);
    }
    e = e01;
    for (; e + 1 < e11; e += 2) {
        const float* ta = T + (size_t)__ldg(&col[e]) * 288 + 192;
        const float* tb = T + (size_t)__ldg(&col[e + 1]) * 288 + 192;
        y0 += __ldg(ta + lane) + __ldg(tb + lane);
        y1 += __ldg(ta + lane + 32) + __ldg(tb + lane + 32);
        y2 += __ldg(ta + lane + 64) + __ldg(tb + lane + 64);
    }
    if (e < e11) {
        const float* ta = T + (size_t)__ldg(&col[e]) * 288 + 192;
        y0 += __ldg(ta + lane);
        y1 += __ldg(ta + lane + 32);
        y2 += __ldg(ta + lane + 64);
    }

    float i0 = 1.f / fmaxf((float)(e01 - e00), 1.f);
    float i1 = 1.f / fmaxf((float)(e11 - e01), 1.f);
    const float* tr = T + (size_t)n * 288;
    float r0 = __ldg(tr + lane), r1 = __ldg(tr + lane + 32), r2 = __ldg(tr + lane + 64);
    float b0 = __ldg(bias + lane), b1 = __ldg(bias + lane + 32), b2 = __ldg(bias + lane + 64);
    float* o = out + (size_t)n * DD;
    o[lane]      = fmaxf(b0 + r0 + x0 * i0 + y0 * i1, 0.f);
    o[lane + 32] = fmaxf(b1 + r1 + x1 * i0 + y1 * i1, 0.f);
    o[lane + 64] = fmaxf(b2 + r2 + x2 * i0 + y2 * i1, 0.f);
}

// ---------------- launch ----------------
extern "C" void kernel_launch(void* const* d_in, const int* in_sizes, int n_in,
                              void* d_out, int out_size) {
    const float* x    = (const float*)d_in[0];
    const int*   ei   = (const int*)d_in[1];
    const float* attr = (const float*)d_in[2];
    const float* Wf   = (const float*)d_in[3];
    const float* bf   = (const float*)d_in[4];
    const float* W    = (const float*)d_in[5];
    const float* root = (const float*)d_in[6];
    const float* bias = (const float*)d_in[7];
    float* out = (float*)d_out;

    int E = in_sizes[1] / 2;
    int N = in_sizes[0] / FF;
    int N2 = 2 * N;

    void *pA, *pB, *pT, *pWfT, *pdg, *prp, *pc, *pcol;
    cudaGetSymbolAddress(&pA, g_hA);
    cudaGetSymbolAddress(&pB, g_hB);
    cudaGetSymbolAddress(&pT, g_T);
    cudaGetSymbolAddress(&pWfT, g_WfT);
    cudaGetSymbolAddress(&pdg, g_deg);
    cudaGetSymbolAddress(&prp, g_rowptr);
    cudaGetSymbolAddress(&pc, g_cur);
    cudaGetSymbolAddress(&pcol, g_col);

    k_prep<<<(N2 + 255) / 256, 256>>>(Wf, (float*)pWfT, (int*)pdg, (int*)pc, N2);
    k_hist<<<(E / 2 + 255) / 256, 256>>>(ei, attr, (int*)pdg, E);
    k_scan<<<1, 1024>>>((int*)pdg, (int*)prp, N2);
    k_fill<<<(E / 2 + 255) / 256, 256>>>(ei, attr, (int*)prp, (int*)pc, (int*)pcol, E);

    int mblocks = (N + 127) / 128;
    k_gemm<<<dim3(mblocks, 1), 256>>>(x, N, FF, (const float*)pWfT, nullptr, nullptr,
                                      (float*)pA, DD, bf, 1);

    const float* W0 = W;
    const float* W1 = W + DD * DD;
    float* hin = (float*)pA;
    float* hout = (float*)pB;
    for (int it = 0; it < 3; it++) {
        k_gemm<<<dim3(mblocks, 3), 256>>>(hin, N, DD, root, W0, W1,
                                          (float*)pT, 3 * DD, nullptr, 0);
        float* o = (it == 2) ? out : hout;
        k_aggout<<<(N * 32 + 255) / 256, 256>>>((const float*)pT, (int*)prp, (int*)pcol,
                                                bias, o, N);
        float* t = hin; hin = hout; hout = t;
    }
}